// round 2
// baseline (speedup 1.0000x reference)
#include <cuda_runtime.h>
#include <cuda_bf16.h>
#include <cstdint>

// Direct ROI-Align from NCHW (no transpose pass).
// Key fact: all 7 bins in an output row share y0/y1, and their x-corners lie
// in a contiguous span of <= 64 floats. Load the two needed rows' spans
// coalesced into smem, then do the bilinear combine from smem.

#define N_B   4
#define C_CH  256
#define H_IN  200
#define W_IN  200
#define HW    (H_IN * W_IN)
#define K_ROI 512
#define OUT_H 7
#define OUT_W 7
#define BINS  (OUT_H * OUT_W)
#define SCALE 0.25f

#define CHUNK 32          // channels per block
#define SPMAX 80          // max span we ever load (true bound ~64)
#define SPTCH 81          // smem pitch (odd -> conflict-free strided access)

__global__ __launch_bounds__(256) void roi_direct(
        const float* __restrict__ inp,
        const float* __restrict__ rois,
        const float* __restrict__ masks,
        float* __restrict__ out) {

    __shared__ float srow[2][CHUNK][SPTCH];     // two input rows x 32 ch x span
    __shared__ float sbuf[CHUNK * BINS];        // output staging [ch][bin]
    __shared__ float s_wxa[OUT_W], s_wxb[OUT_W], s_m[OUT_W];
    __shared__ int   s_xa[OUT_W];
    __shared__ int   s_yA;
    __shared__ float s_wy0, s_wy1;

    const int k    = blockIdx.x;
    const int c0   = blockIdx.y * CHUNK;
    const int t    = threadIdx.x;
    const int lane = t & 31;
    const int warp = t >> 5;

    // roi constants (computed redundantly by all threads; cheap)
    const int   b   = (int)rois[k * 5 + 0];
    const float fx1 = rois[k * 5 + 1] * SCALE;
    const float fy1 = rois[k * 5 + 2] * SCALE;
    const float fx2 = rois[k * 5 + 3] * SCALE;
    const float fy2 = rois[k * 5 + 4] * SCALE;
    const float bw  = fmaxf(fx2 - fx1, 1.0f) * (1.0f / OUT_W);
    const float bh  = fmaxf(fy2 - fy1, 1.0f) * (1.0f / OUT_H);

    const float* plane0 = inp + ((size_t)b * C_CH + c0) * HW;

    for (int br = 0; br < OUT_H; ++br) {
        // ---- per-bin-row precompute (threads 0..6) ----
        if (t < OUT_W) {
            const int ow = t;
            const float xs  = fx1 + ((float)ow + 0.5f) * bw;
            const float x0f = floorf(xs);
            const float lx  = xs - x0f;
            int x0 = min(max((int)x0f, 0), W_IN - 1);
            int   xa;
            float wxa, wxb;
            if (x0 >= W_IN - 1) { xa = W_IN - 2; wxa = 0.0f; wxb = 1.0f; }
            else                { xa = x0;       wxa = 1.0f - lx; wxb = lx; }
            s_xa[ow]  = xa;
            s_wxa[ow] = wxa;
            s_wxb[ow] = wxb;
            s_m[ow]   = masks[k * BINS + br * OUT_W + ow];
            if (ow == 0) {
                const float ys  = fy1 + ((float)br + 0.5f) * bh;
                const float y0f = floorf(ys);
                const float ly  = ys - y0f;
                int y0 = min(max((int)y0f, 0), H_IN - 1);
                if (y0 >= H_IN - 1) { s_yA = H_IN - 2; s_wy0 = 0.0f; s_wy1 = 1.0f; }
                else                { s_yA = y0;       s_wy0 = 1.0f - ly; s_wy1 = ly; }
            }
        }
        __syncthreads();

        // ---- coalesced load of the two row spans for 32 channels ----
        const int xlo = s_xa[0];
        const int S   = s_xa[OUT_W - 1] + 2 - xlo;   // <= 64 by construction
        const int yA  = s_yA;
        const float* rbase = plane0 + (size_t)yA * W_IN + xlo;

        // 64 (row, channel) pairs spread over 8 warps; lanes sweep the span.
        for (int pr = warp; pr < 2 * CHUNK; pr += 8) {
            const int r  = pr >> 5;       // 0..1
            const int ch = pr & 31;
            const float* src = rbase + (size_t)ch * HW + r * W_IN;
            float* dst = srow[r][ch];
            for (int xx = lane; xx < S; xx += 32)
                dst[xx] = __ldg(src + xx);
        }
        __syncthreads();

        // ---- bilinear combine: 7 bins x 32 channels ----
        {
            const int cc = t & 31;
            const int ow = t >> 5;        // 0..7 (ow==7 idle)
            if (ow < OUT_W) {
                const int   ia  = s_xa[ow] - xlo;
                const float wxa = s_wxa[ow];
                const float wxb = s_wxb[ow];
                const float v0  = srow[0][cc][ia] * wxa + srow[0][cc][ia + 1] * wxb;
                const float v1  = srow[1][cc][ia] * wxa + srow[1][cc][ia + 1] * wxb;
                sbuf[cc * BINS + br * OUT_W + ow] = (s_wy0 * v0 + s_wy1 * v1) * s_m[ow];
            }
        }
        __syncthreads();
    }

    // ---- contiguous coalesced store: 32 channels x 49 bins ----
    float* o = out + ((size_t)k * C_CH + c0) * BINS;
#pragma unroll 4
    for (int i = t; i < CHUNK * BINS; i += 256)
        o[i] = sbuf[i];
}

extern "C" void kernel_launch(void* const* d_in, const int* in_sizes, int n_in,
                              void* d_out, int out_size) {
    const float* inputs = (const float*)d_in[0];  // [4,256,200,200]
    const float* rois   = (const float*)d_in[1];  // [512,5]
    const float* masks  = (const float*)d_in[2];  // [512,7,7]
    float* out = (float*)d_out;                   // [512,256,7,7]

    (void)in_sizes; (void)n_in; (void)out_size;

    dim3 grid(K_ROI, C_CH / CHUNK);               // 512 x 8 = 4096 blocks
    roi_direct<<<grid, 256>>>(inputs, rois, masks, out);
}

// round 3
// speedup vs baseline: 1.4675x; 1.4675x over previous
#include <cuda_runtime.h>
#include <cuda_bf16.h>
#include <cstdint>

// Direct ROI-Align from NCHW, single kernel.
// Per block: one roi x 32 channels. For each of the 7 output rows, the two
// needed input rows' x-span (<=68 floats, 16B-aligned) is loaded coalesced as
// float4 into double-buffered smem; bilinear combine reads smem; output is
// staged and written contiguously.

#define N_B   4
#define C_CH  256
#define H_IN  200
#define W_IN  200
#define HW    (H_IN * W_IN)
#define K_ROI 512
#define OUT_H 7
#define OUT_W 7
#define BINS  (OUT_H * OUT_W)
#define SCALE 0.25f

#define CHUNK 32
#define SP4   17            // max float4 quads per span (span <= 67 floats)
#define PITCH (SP4 * 4)     // 68 floats; ch*PITCH*4B = 272*ch -> 16B aligned

__global__ __launch_bounds__(256, 5) void roi_direct(
        const float* __restrict__ inp,
        const float* __restrict__ rois,
        const float* __restrict__ masks,
        float* __restrict__ out) {

    __shared__ float srow[2][2][CHUNK][PITCH];   // [buf][row][ch][pos] 34816 B
    __shared__ float sbuf[CHUNK * BINS];         // 6272 B
    __shared__ int   s_xa[OUT_W];
    __shared__ float s_wxa[OUT_W], s_wxb[OUT_W];
    __shared__ int   s_yA[OUT_H];
    __shared__ float s_wy0[OUT_H], s_wy1[OUT_H];
    __shared__ float s_m[BINS];

    const int k  = blockIdx.x;
    const int c0 = blockIdx.y * CHUNK;
    const int t  = threadIdx.x;

    // ---------------- prologue: all per-roi metadata, one barrier ----------
    if (t < 16) {
        const float fx1 = rois[k * 5 + 1] * SCALE;
        const float fy1 = rois[k * 5 + 2] * SCALE;
        const float fx2 = rois[k * 5 + 3] * SCALE;
        const float fy2 = rois[k * 5 + 4] * SCALE;
        const float bw  = fmaxf(fx2 - fx1, 1.0f) * (1.0f / OUT_W);
        const float bh  = fmaxf(fy2 - fy1, 1.0f) * (1.0f / OUT_H);

        const int  j   = t & 7;
        const bool isx = (t < 8);
        if (j < 7) {
            const float lo  = isx ? fx1 : fy1;
            const float bsz = isx ? bw  : bh;
            const int   LIM = isx ? (W_IN - 1) : (H_IN - 1);
            const float s   = lo + ((float)j + 0.5f) * bsz;
            const float f   = floorf(s);
            const float l   = s - f;
            int   i0 = max((int)f, 0);
            int   ia; float wa, wb;
            if (i0 >= LIM) { ia = LIM - 1; wa = 0.0f;     wb = 1.0f; }
            else           { ia = i0;      wa = 1.0f - l; wb = l;    }
            if (isx) { s_xa[j] = ia; s_wxa[j] = wa; s_wxb[j] = wb; }
            else     { s_yA[j] = ia; s_wy0[j] = wa; s_wy1[j] = wb; }
        }
    }
    if (t >= 64 && t < 64 + BINS)
        s_m[t - 64] = masks[k * BINS + (t - 64)];
    __syncthreads();

    const int b     = (int)rois[k * 5];          // broadcast load
    const int xlo4  = s_xa[0] & ~3;              // 16B-aligned span start
    const int S4    = (s_xa[OUT_W - 1] + 5 - xlo4) >> 2;   // quads needed

    // static load-thread mapping: 4 threads per (row, channel)
    const int rc    = t >> 2;                    // 0..63
    const int lr    = rc >> 5;                   // 0..1  (which of the 2 rows)
    const int lch   = rc & 31;                   // channel within chunk
    const int qlane = t & 3;
    const float* lsrc0 = inp + ((size_t)(b * C_CH + c0 + lch)) * HW + xlo4;

    // combine-thread mapping
    const int cc = t & 31;
    const int ow = t >> 5;                       // 0..7 (7 = idle)

    // ---------------- pipelined row loop (1 barrier / row) -----------------
    // load row-pair 0 into buf 0
    {
        const float* src = lsrc0 + (size_t)(s_yA[0] + lr) * W_IN;
        float* dst = srow[0][lr][lch];
        for (int q = qlane; q < S4; q += 4) {
            const int cx = min(4 * q, W_IN - 4 - xlo4);   // clamp: unused quads only
            *(float4*)(dst + 4 * q) = *(const float4*)(src + cx);
        }
    }
    __syncthreads();

#pragma unroll
    for (int br = 0; br < OUT_H; ++br) {
        const int cur = br & 1;
        // prefetch next row-pair into the other buffer (issued before combine)
        if (br < OUT_H - 1) {
            const float* src = lsrc0 + (size_t)(s_yA[br + 1] + lr) * W_IN;
            float* dst = srow[cur ^ 1][lr][lch];
            for (int q = qlane; q < S4; q += 4) {
                const int cx = min(4 * q, W_IN - 4 - xlo4);
                *(float4*)(dst + 4 * q) = *(const float4*)(src + cx);
            }
        }
        // combine current row-pair
        if (ow < OUT_W) {
            const int   ia  = s_xa[ow] - xlo4;
            const float wxa = s_wxa[ow];
            const float wxb = s_wxb[ow];
            const float* r0 = srow[cur][0][cc];
            const float* r1 = srow[cur][1][cc];
            const float v0  = r0[ia] * wxa + r0[ia + 1] * wxb;
            const float v1  = r1[ia] * wxa + r1[ia + 1] * wxb;
            sbuf[cc * BINS + br * OUT_W + ow] =
                (s_wy0[br] * v0 + s_wy1[br] * v1) * s_m[br * OUT_W + ow];
        }
        __syncthreads();
    }

    // ---------------- contiguous output store -----------------------------
    float* o = out + ((size_t)k * C_CH + c0) * BINS;
#pragma unroll
    for (int i = t; i < CHUNK * BINS; i += 256)
        o[i] = sbuf[i];
}

extern "C" void kernel_launch(void* const* d_in, const int* in_sizes, int n_in,
                              void* d_out, int out_size) {
    const float* inputs = (const float*)d_in[0];  // [4,256,200,200]
    const float* rois   = (const float*)d_in[1];  // [512,5]
    const float* masks  = (const float*)d_in[2];  // [512,7,7]
    float* out = (float*)d_out;                   // [512,256,7,7]

    (void)in_sizes; (void)n_in; (void)out_size;

    dim3 grid(K_ROI, C_CH / CHUNK);               // 512 x 8 = 4096 blocks
    roi_direct<<<grid, 256>>>(inputs, rois, masks, out);
}